// round 8
// baseline (speedup 1.0000x reference)
#include <cuda_runtime.h>
#include <cuda_fp16.h>
#include <math.h>

#define N_NODES 100000
#define E_EDGES 3200000

// ---------------- scratch (device globals; allocation-free) ----------------
__device__ __align__(16) uint4 g_h1h[N_NODES * 2];   // layer1 h: 16 fp16 = 32B/row
__device__ __align__(16) uint4 g_h2h[N_NODES * 2];   // layer2 row: 10 fp16 + asrc2(f32 @ u[5]) + pad
__device__ float g_asrc1[N_NODES];
__device__ float g_adst1[N_NODES];
__device__ float g_adst2[N_NODES];
__device__ int   g_cnt[N_NODES];          // zeroed at BSS init; re-zeroed by k_scatter each run
__device__ int   g_rowstart[N_NODES + 1];
__device__ int   g_cursor[N_NODES];
__device__ unsigned g_flag[512];          // lookback flags; re-zeroed by k_scatter each run
__device__ int   g_csr[E_EDGES];          // src per edge grouped by dst (self loops implicit)

// ---------------- helpers ----------------
__device__ __forceinline__ unsigned ld_acq(unsigned* p) {
    unsigned v;
    asm volatile("ld.acquire.gpu.global.u32 %0, [%1];" : "=r"(v) : "l"(p) : "memory");
    return v;
}
__device__ __forceinline__ void st_rel(unsigned* p, unsigned v) {
    asm volatile("st.release.gpu.global.u32 [%0], %1;" :: "l"(p), "r"(v) : "memory");
}
__device__ __forceinline__ unsigned pack2(float a, float b) {
    __half2 h = __floats2half2_rn(a, b);
    return *(unsigned*)&h;
}
__device__ __forceinline__ void acc8(uint4 r, float w, float* acc) {
    float2 p;
    p = __half22float2(*(__half2*)&r.x); acc[0] += w * p.x; acc[1] += w * p.y;
    p = __half22float2(*(__half2*)&r.y); acc[2] += w * p.x; acc[3] += w * p.y;
    p = __half22float2(*(__half2*)&r.z); acc[4] += w * p.x; acc[5] += w * p.y;
    p = __half22float2(*(__half2*)&r.w); acc[6] += w * p.x; acc[7] += w * p.y;
}

// ---------------- kernel 1: hist + node1 fused (independent work) ----------------
__global__ void k_front(const float* __restrict__ x, const float* __restrict__ W1,
                        const float* __restrict__ a1s, const float* __restrict__ a1d,
                        const int* __restrict__ ei, int N, int E, int nbH) {
    if ((int)blockIdx.x < nbH) {   // histogram part
        int k = blockIdx.x * 256 + threadIdx.x;
        if (k < E) atomicAdd(g_cnt + __ldg(ei + E + k), 1);
        return;
    }
    // node1 part: h1 = x @ W1 (fp32 math, fp16 store); asrc1/adst1. One warp per node.
    __shared__ float sWT[16 * 128];   // sWT[f*128 + k] = W1[k*16 + f]
    for (int i = threadIdx.x; i < 2048; i += blockDim.x) {
        int k = i >> 4, f = i & 15;
        sWT[f * 128 + k] = W1[i];
    }
    __syncthreads();
    int node = (blockIdx.x - nbH) * 8 + (threadIdx.x >> 5);
    int lane = threadIdx.x & 31;
    if (node >= N) return;
    float4 v = __ldg((const float4*)(x + (size_t)node * 128) + lane);
    float hout[16];
#pragma unroll
    for (int f = 0; f < 16; f++) {
        float4 wv = *((const float4*)(sWT + f * 128) + lane);
        float p = v.x * wv.x + v.y * wv.y + v.z * wv.z + v.w * wv.w;
#pragma unroll
        for (int off = 16; off; off >>= 1) p += __shfl_xor_sync(0xffffffffu, p, off);
        hout[f] = p;
    }
    if (lane == 0) {
        uint4 u0, u1;
        u0.x = pack2(hout[0], hout[1]);   u0.y = pack2(hout[2], hout[3]);
        u0.z = pack2(hout[4], hout[5]);   u0.w = pack2(hout[6], hout[7]);
        u1.x = pack2(hout[8], hout[9]);   u1.y = pack2(hout[10], hout[11]);
        u1.z = pack2(hout[12], hout[13]); u1.w = pack2(hout[14], hout[15]);
        g_h1h[node * 2 + 0] = u0;
        g_h1h[node * 2 + 1] = u1;
        float s = 0.0f, d = 0.0f;
#pragma unroll
        for (int f = 0; f < 16; f++) { s += hout[f] * __ldg(a1s + f); d += hout[f] * __ldg(a1d + f); }
        g_asrc1[node] = s; g_adst1[node] = d;
    }
}

// ---------------- kernel 2: single-pass exclusive scan (decoupled lookback) ----------------
__global__ void k_scan(int N, int E) {
    __shared__ int s[256];
    __shared__ int s_prefix;
    int tid = threadIdx.x, b = blockIdx.x;
    int i = b * 256 + tid;
    int v = (i < N) ? g_cnt[i] : 0;
    s[tid] = v;
    __syncthreads();
#pragma unroll
    for (int o = 1; o < 256; o <<= 1) {
        int t = (tid >= o) ? s[tid - o] : 0;
        __syncthreads();
        s[tid] += t;
        __syncthreads();
    }
    int total = s[255];
    if (tid == 0) {
        if (b == 0) {
            st_rel(&g_flag[0], (2u << 30) | (unsigned)total);
            s_prefix = 0;
            g_rowstart[N] = E;
        } else {
            st_rel(&g_flag[b], (1u << 30) | (unsigned)total);
            int run = 0, idx = b - 1;
            while (true) {
                unsigned f = ld_acq(&g_flag[idx]);
                unsigned st = f >> 30;
                if (st == 2u) { run += (int)(f & 0x3FFFFFFFu); break; }
                if (st == 1u) { run += (int)(f & 0x3FFFFFFFu); idx--; }
            }
            st_rel(&g_flag[b], (2u << 30) | (unsigned)(run + total));
            s_prefix = run;
        }
    }
    __syncthreads();
    int pre = s_prefix;
    if (i < N) {
        int r = s[tid] - v + pre;
        g_rowstart[i] = r;
        g_cursor[i] = r;
    }
}

// ---------------- kernel 3: scatter + re-zero cnt/flags for next replay ----------------
__global__ void k_scatter(const int* __restrict__ ei, int E, int N, int nbS) {
    if ((int)blockIdx.x < nbS) {
        int k = blockIdx.x * 256 + threadIdx.x;
        if (k >= E) return;
        int s = __ldg(ei + k), d = __ldg(ei + E + k);
        g_csr[atomicAdd(g_cursor + d, 1)] = s;
    } else {
        int z = (blockIdx.x - nbS) * 256 + threadIdx.x;
        if (z < N) g_cnt[z] = 0;
        if (z < 512) g_flag[z] = 0;
    }
}

// ---------------- kernel 4: layer1 aggregation + fused mid epilogue ----------------
__global__ void k_agg1(const float* __restrict__ b1, const float* __restrict__ W2,
                       const float* __restrict__ a2s, const float* __restrict__ a2d, int N) {
    int node = (blockIdx.x * blockDim.x + threadIdx.x) >> 5;
    if (node >= N) return;
    int lane = threadIdx.x & 31;
    int pair = lane >> 1, sub = lane & 1;
    int start = __ldg(g_rowstart + node);
    int end   = __ldg(g_rowstart + node + 1);
    float ad = g_adst1[node];

    float acc[8];
#pragma unroll
    for (int f = 0; f < 8; f++) acc[f] = 0.0f;
    float den = 0.0f;

    // per-lane independent work: loop divergence among pairs is safe (no intra-loop shfl)
    for (int j = start + pair; j < end; j += 16) {
        int s = __ldg(g_csr + j);
        float e = __ldg(g_asrc1 + s) + ad;
        e = (e > 0.0f) ? e : 0.2f * e;
        float w = __expf(e);
        if (sub == 0) den += w;
        uint4 r = __ldg(g_h1h + s * 2 + sub);
        acc8(r, w, acc);
    }
    if (pair == 0) {   // self loop (no shfl inside)
        float e = __ldg(g_asrc1 + node) + ad;
        e = (e > 0.0f) ? e : 0.2f * e;
        float w = __expf(e);
        if (sub == 0) den += w;
        uint4 r = __ldg(g_h1h + node * 2 + sub);
        acc8(r, w, acc);
    }
#pragma unroll
    for (int o = 16; o >= 2; o >>= 1)
#pragma unroll
        for (int f = 0; f < 8; f++) acc[f] += __shfl_xor_sync(0xffffffffu, acc[f], o);
#pragma unroll
    for (int o = 16; o >= 1; o >>= 1) den += __shfl_xor_sync(0xffffffffu, den, o);

    // fused mid: g = relu(o1 + b1); h2 = g @ W2; asrc2/adst2; fp16 row (+asrc2 packed)
    float inv = 1.0f / den;
    float g[16];
#pragma unroll
    for (int f = 0; f < 8; f++) {
        g[f]     = __shfl_sync(0xffffffffu, acc[f], 0);
        g[f + 8] = __shfl_sync(0xffffffffu, acc[f], 1);
    }
#pragma unroll
    for (int f = 0; f < 16; f++) g[f] = fmaxf(g[f] * inv + __ldg(b1 + f), 0.0f);

    float h = 0.0f;
    if (lane < 10) {
#pragma unroll
        for (int f = 0; f < 16; f++) h += g[f] * __ldg(W2 + f * 10 + lane);
    }
    float sc = (lane < 10) ? h * __ldg(a2s + lane) : 0.0f;
    float dc = (lane < 10) ? h * __ldg(a2d + lane) : 0.0f;
#pragma unroll
    for (int o = 16; o >= 1; o >>= 1) {
        sc += __shfl_xor_sync(0xffffffffu, sc, o);
        dc += __shfl_xor_sync(0xffffffffu, dc, o);
    }
    float hv = (lane < 10) ? h : 0.0f;
    float p0 = __shfl_sync(0xffffffffu, hv, (2 * lane) & 31);
    float p1 = __shfl_sync(0xffffffffu, hv, (2 * lane + 1) & 31);
    unsigned* row = (unsigned*)(g_h2h + node * 2);
    if (lane < 5)       row[lane] = pack2(p0, p1);
    else if (lane == 5) row[5] = __float_as_uint(sc);   // asrc2 packed into row
    else if (lane < 8)  row[lane] = 0u;
    if (lane == 0) g_adst2[node] = dc;
}

// ---------------- kernel 5: layer2 aggregation + fused MLP head ----------------
__global__ void k_agg2(const float* __restrict__ b2,
                       const float* __restrict__ Wl1, const float* __restrict__ bl1,
                       const float* __restrict__ Wl2, const float* __restrict__ bl2,
                       float* __restrict__ out, int N) {
    int node = (blockIdx.x * blockDim.x + threadIdx.x) >> 5;
    if (node >= N) return;
    int lane = threadIdx.x & 31;
    int pair = lane >> 1, sub = lane & 1;
    int start = __ldg(g_rowstart + node);
    int end   = __ldg(g_rowstart + node + 1);
    float ad = g_adst2[node];

    float acc[8];
#pragma unroll
    for (int f = 0; f < 8; f++) acc[f] = 0.0f;
    float den = 0.0f;

    // WARP-UNIFORM loop: every lane runs every iteration so the shfl is safe.
    for (int base = start; base < end; base += 16) {
        int j = base + pair;
        bool val = (j < end);
        int s = val ? __ldg(g_csr + j) : node;   // safe dummy index when out of range
        uint4 r = __ldg(g_h2h + (size_t)s * 2 + sub);
        float w = 0.0f;
        if (sub == 1) {   // r = {pack(h8,h9), asrc2, 0, 0}
            float e = __uint_as_float(r.y) + ad;
            e = (e > 0.0f) ? e : 0.2f * e;
            w = val ? __expf(e) : 0.0f;
            den += w;
            r.y = 0u; r.z = 0u; r.w = 0u;
        }
        float wo = __shfl_xor_sync(0xffffffffu, w, 1);   // uniform: all 32 lanes here
        if (sub == 0) w = wo;
        acc8(r, w, acc);
    }
    {   // self loop: all lanes compute w locally (no shfl); only pair 0 accumulates
        uint4 u1 = __ldg(g_h2h + (size_t)node * 2 + 1);
        float e = __uint_as_float(u1.y) + ad;
        e = (e > 0.0f) ? e : 0.2f * e;
        float w = __expf(e);
        if (pair == 0) {
            uint4 r = (sub == 0) ? __ldg(g_h2h + (size_t)node * 2) : u1;
            if (sub == 1) { den += w; r.y = 0u; r.z = 0u; r.w = 0u; }
            acc8(r, w, acc);
        }
    }
#pragma unroll
    for (int o = 16; o >= 2; o >>= 1)
#pragma unroll
        for (int f = 0; f < 8; f++) acc[f] += __shfl_xor_sync(0xffffffffu, acc[f], o);
#pragma unroll
    for (int o = 16; o >= 1; o >>= 1) den += __shfl_xor_sync(0xffffffffu, den, o);

    // fused final: a = o2 + b2; z = relu(a@Wl1 + bl1); out = z@Wl2 + bl2
    float inv = 1.0f / den;
    float a[10];
#pragma unroll
    for (int f = 0; f < 8; f++) a[f] = __shfl_sync(0xffffffffu, acc[f], 0) * inv + __ldg(b2 + f);
    a[8] = __shfl_sync(0xffffffffu, acc[0], 1) * inv + __ldg(b2 + 8);
    a[9] = __shfl_sync(0xffffffffu, acc[1], 1) * inv + __ldg(b2 + 9);
    float oc = 0.0f;
    if (lane < 10) {
        float z = __ldg(bl1 + lane);
#pragma unroll
        for (int f = 0; f < 10; f++) z += a[f] * __ldg(Wl1 + f * 10 + lane);
        oc = fmaxf(z, 0.0f) * __ldg(Wl2 + lane);
    }
#pragma unroll
    for (int o = 16; o >= 1; o >>= 1) oc += __shfl_xor_sync(0xffffffffu, oc, o);
    if (lane == 0) out[node] = oc + __ldg(bl2);
}

// ---------------- launch ----------------
extern "C" void kernel_launch(void* const* d_in, const int* in_sizes, int n_in,
                              void* d_out, int out_size) {
    const float* x   = (const float*)d_in[0];
    const int*   ei  = (const int*)d_in[1];      // int32
    const float* W1  = (const float*)d_in[2];
    const float* a1s = (const float*)d_in[3];
    const float* a1d = (const float*)d_in[4];
    const float* b1  = (const float*)d_in[5];
    const float* W2  = (const float*)d_in[6];
    const float* a2s = (const float*)d_in[7];
    const float* a2d = (const float*)d_in[8];
    const float* b2  = (const float*)d_in[9];
    const float* Wl1 = (const float*)d_in[10];
    const float* bl1 = (const float*)d_in[11];
    const float* Wl2 = (const float*)d_in[12];
    const float* bl2 = (const float*)d_in[13];
    float* out = (float*)d_out;

    int N = in_sizes[0] / 128;
    int E = in_sizes[1] / 2;
    int nbH = (E + 255) / 256;          // hist blocks
    int nbN = (N + 7) / 8;              // node/agg blocks (8 warps, 1 node/warp)
    int nbZ = (N + 255) / 256;          // zero/scan blocks

    k_front  <<<nbH + nbN, 256>>>(x, W1, a1s, a1d, ei, N, E, nbH);
    k_scan   <<<nbZ, 256>>>(N, E);
    k_scatter<<<nbH + nbZ, 256>>>(ei, E, N, nbH);
    k_agg1   <<<nbN, 256>>>(b1, W2, a2s, a2d, N);
    k_agg2   <<<nbN, 256>>>(b2, Wl1, bl1, Wl2, bl2, out, N);
}